// round 6
// baseline (speedup 1.0000x reference)
#include <cuda_runtime.h>
#include <cuda_bf16.h>
#include <cstdint>

#define DD 64
#define KC 512
#define ROWSB 128
#define NTHR 288          // 9 warps: 0-3 epilogue(S), 4-7 loader(L), 8 MMA issuer
#define NCTA 148
#define CAP 16
#define MARGIN 5e-3f

#if defined(__CUDA_ARCH__) && (defined(__CUDA_ARCH_FEAT_SM103_ALL) || defined(__CUDA_ARCH_FEAT_SM100_ALL) || defined(__CUDA_ARCH_FEAT_SM101_ALL))
#define HAS_TCGEN05 1
#else
#define HAS_TCGEN05 0
#endif

// ---- smem byte offsets ----
#define MB_DFULL(q)  ((q) * 8)          // count 1 (commit), flips once/tile
#define MB_DFREE(q)  (32 + (q) * 8)     // count 128 (S),   flips once/tile
#define MB_ARDY(b)   (64 + (b) * 8)     // count 128 (L),   flips once/2 tiles
#define MB_AFREE(b)  (80 + (b) * 8)     // count 128 (S),   flips once/2 tiles
#define TMEM_SLOT    96
#define CS_OFF       128                 // 512 f32
#define XS_OFF       2176                // 2 x 128 f32
#define B_OFF        4096                // 64KB bf16 h-limb, SW128
#define A_OFF(b)     (69632 + (b) * 16384)
#define SMEM_TOTAL   102400

__device__ __forceinline__ uint32_t smem_u32(const void* p) {
    uint32_t a;
    asm("{ .reg .u64 t; cvta.to.shared.u64 t, %1; cvt.u32.u64 %0, t; }" : "=r"(a) : "l"(p));
    return a;
}
__device__ __forceinline__ uint32_t sw128(uint32_t off) { return off ^ ((off >> 3) & 0x70); }

#if HAS_TCGEN05
__device__ __forceinline__ uint32_t elect1() {
    uint32_t p;
    asm volatile("{ .reg .pred p; elect.sync _|p, 0xFFFFFFFF; selp.b32 %0, 1, 0, p; }" : "=r"(p));
    return p;
}
__device__ __forceinline__ void mbar_init(uint32_t a, uint32_t cnt) {
    asm volatile("mbarrier.init.shared.b64 [%0], %1;" :: "r"(a), "r"(cnt) : "memory");
}
__device__ __forceinline__ void mbar_arrive(uint32_t a) {
    asm volatile("mbarrier.arrive.release.cta.shared::cta.b64 _, [%0];" :: "r"(a) : "memory");
}
__device__ __forceinline__ void mbar_wait(uint32_t a, uint32_t parity) {
    asm volatile(
        "{\n\t.reg .pred P;\n"
        "WL_%=:\n\t"
        "mbarrier.try_wait.parity.acquire.cta.shared::cta.b64 P, [%0], %1, 0x989680;\n\t"
        "@!P bra WL_%=;\n\t}"
        :: "r"(a), "r"(parity) : "memory");
}
__device__ __forceinline__ void fence_async() {
    asm volatile("fence.proxy.async.shared::cta;" ::: "memory");
}
__device__ __forceinline__ void tmem_alloc(uint32_t slot, uint32_t ncols) {
    asm volatile("tcgen05.alloc.cta_group::1.sync.aligned.shared::cta.b32 [%0], %1;"
                 :: "r"(slot), "r"(ncols) : "memory");
}
__device__ __forceinline__ void tmem_dealloc(uint32_t base, uint32_t ncols) {
    asm volatile("tcgen05.dealloc.cta_group::1.sync.aligned.b32 %0, %1;" :: "r"(base), "r"(ncols));
}
__device__ __forceinline__ void mma_f16_ss(uint32_t d, uint64_t ad, uint64_t bd,
                                           uint32_t idesc, uint32_t en) {
    asm volatile(
        "{\n\t.reg .pred p;\n\t"
        "setp.ne.u32 p, %5, 0;\n\t"
        "tcgen05.mma.cta_group::1.kind::f16 [%0], %1, %2, %3, {%4, %4, %4, %4}, p;\n\t}"
        :: "r"(d), "l"(ad), "l"(bd), "r"(idesc), "r"(0u), "r"(en) : "memory");
}
__device__ __forceinline__ void mma_commit(uint32_t mbar) {
    asm volatile("tcgen05.commit.cta_group::1.mbarrier::arrive::one.shared::cluster.b64 [%0];"
                 :: "r"(mbar) : "memory");
}
__device__ __forceinline__ void fence_tc_after() {
    asm volatile("tcgen05.fence::after_thread_sync;" ::: "memory");
}
__device__ __forceinline__ void fence_tc_before() {
    asm volatile("tcgen05.fence::before_thread_sync;" ::: "memory");
}
#define LDTM_X32(r, a) \
    asm volatile("tcgen05.ld.sync.aligned.32x32b.x32.b32 " \
        "{%0,%1,%2,%3,%4,%5,%6,%7,%8,%9,%10,%11,%12,%13,%14,%15," \
        "%16,%17,%18,%19,%20,%21,%22,%23,%24,%25,%26,%27,%28,%29,%30,%31}, [%32];" \
        : "=r"((r)[0]),"=r"((r)[1]),"=r"((r)[2]),"=r"((r)[3]),"=r"((r)[4]),"=r"((r)[5]), \
          "=r"((r)[6]),"=r"((r)[7]),"=r"((r)[8]),"=r"((r)[9]),"=r"((r)[10]),"=r"((r)[11]), \
          "=r"((r)[12]),"=r"((r)[13]),"=r"((r)[14]),"=r"((r)[15]),"=r"((r)[16]),"=r"((r)[17]), \
          "=r"((r)[18]),"=r"((r)[19]),"=r"((r)[20]),"=r"((r)[21]),"=r"((r)[22]),"=r"((r)[23]), \
          "=r"((r)[24]),"=r"((r)[25]),"=r"((r)[26]),"=r"((r)[27]),"=r"((r)[28]),"=r"((r)[29]), \
          "=r"((r)[30]),"=r"((r)[31]) : "r"(a))
__device__ __forceinline__ void tmem_wait_ld() {
    asm volatile("tcgen05.wait::ld.sync.aligned;" ::: "memory");
}
#endif

#define DESC_BASE 0x4000404000010000ULL
__device__ __forceinline__ uint64_t mk_desc(uint32_t addr) {
    return DESC_BASE | ((uint64_t)(addr >> 4) & 0x3FFF);
}
#define IDESC 0x8200490u   // f32 acc, bf16 a/b, M=128, N=128 (proven R3/R4)

__device__ __forceinline__ uint32_t packbf(float a, float b) {
    return (uint32_t)__bfloat16_as_ushort(__float2bfloat16(a)) |
           ((uint32_t)__bfloat16_as_ushort(__float2bfloat16(b)) << 16);
}

__global__ void __launch_bounds__(NTHR, 1)
vq_persist(const float* __restrict__ x, const float* __restrict__ cbk,
           float* __restrict__ out, int n) {
    extern __shared__ char smem[];
    const int tid = threadIdx.x;
    const int bid = blockIdx.x;
    const size_t nD = (size_t)n * DD;
    float* Cs = (float*)(smem + CS_OFF);

#if HAS_TCGEN05
    const uint32_t sb = smem_u32(smem);
    const int wid = tid >> 5;
    float* XsS = (float*)(smem + XS_OFF);

    const int ntiles = (n + ROWSB - 1) / ROWSB;
    const int nt = (ntiles > bid) ? (ntiles - bid + NCTA - 1) / NCTA : 0;

    // ---------- startup: barriers, TMEM, B h-limb, exact csq ----------
    if (tid == 0) {
        for (int q = 0; q < 4; ++q) { mbar_init(sb + MB_DFULL(q), 1); mbar_init(sb + MB_DFREE(q), 128); }
        for (int b = 0; b < 2; ++b) { mbar_init(sb + MB_ARDY(b), 128); mbar_init(sb + MB_AFREE(b), 128); }
    }
    __syncthreads();
    if (wid == 8) tmem_alloc(sb + TMEM_SLOT, 512);

    // B h-limb: 512x64 -> bf16 SW128 (rows = codes, 128B/row)
    for (int i = tid; i < KC * DD / 4; i += NTHR) {
        int code = i >> 4, kq = i & 15;
        float4 v = __ldg(((const float4*)cbk) + i);
        uint32_t lo = packbf(v.x, v.y), hi = packbf(v.z, v.w);
        uint64_t u = (uint64_t)lo | ((uint64_t)hi << 32);
        *(uint64_t*)(smem + B_OFF + sw128(code * 128 + kq * 8)) = u;
    }
    // exact csq (reference rounding order)
    for (int c = tid; c < KC; c += NTHR) {
        float s = 0.0f;
        const float* cr = cbk + c * DD;
        for (int k = 0; k < DD; ++k) {
            float v = __ldg(cr + k);
            s = __fadd_rn(s, __fmul_rn(v, v));
        }
        Cs[c] = s;
    }
    fence_async();
    __syncthreads();
    const uint32_t tmem = *(volatile uint32_t*)(smem + TMEM_SLOT);

    if (wid < 4) {
        // ================= S: epilogue, thread = row =================
        const int row = tid;
        for (int it = 0; it < nt; ++it) {
            const int tile = bid + it * NCTA;
            const int grow = tile * ROWSB + row;
            const int buf = it & 1;
            mbar_wait(sb + MB_ARDY(buf), (uint32_t)((it >> 1) & 1));
            const float xs = XsS[buf * 128 + row];

            float runmin = 3.4e38f, thrv = 3.4e38f;
            float cd[CAP]; int cc[CAP]; int ncnt = 0;

            for (int q = 0; q < 4; ++q) {
                mbar_wait(sb + MB_DFULL(q), (uint32_t)(it & 1));
                fence_tc_after();
                #pragma unroll
                for (int b = 0; b < 4; ++b) {
                    uint32_t rg[32];
                    LDTM_X32(rg, tmem + q * 128 + b * 32);
                    tmem_wait_ld();
                    const int base = q * 128 + b * 32;
                    #pragma unroll
                    for (int j4 = 0; j4 < 8; ++j4) {
                        float4 cs4 = *(const float4*)(Cs + base + j4 * 4);
                        #pragma unroll
                        for (int jj = 0; jj < 4; ++jj) {
                            const int j = j4 * 4 + jj;
                            float csv = (jj == 0) ? cs4.x : (jj == 1) ? cs4.y : (jj == 2) ? cs4.z : cs4.w;
                            float dot = __uint_as_float(rg[j]);
                            float dist = __fmaf_rn(-2.0f, dot, xs + csv);
                            if (dist <= thrv) {   // rare
                                if (ncnt < CAP) {
                                    cd[ncnt] = dist; cc[ncnt] = base + j; ++ncnt;
                                } else {
                                    // evict-max: transients (beyond final margin) are
                                    // strictly larger than needed entries, so the max
                                    // is always safe to evict; a new running-min always
                                    // beats the max, so the min is never dropped.
                                    int mi = 0; float mv = cd[0];
                                    #pragma unroll
                                    for (int i2 = 1; i2 < CAP; ++i2)
                                        if (cd[i2] > mv) { mv = cd[i2]; mi = i2; }
                                    if (dist < mv) { cd[mi] = dist; cc[mi] = base + j; }
                                }
                                if (dist < runmin) { runmin = dist; thrv = runmin + MARGIN; }
                            }
                        }
                    }
                }
                fence_tc_before();
                mbar_arrive(sb + MB_DFREE(q));
            }

            // exact refine; tie-break in-comparison (lowest code index), order-free
            if (grow < n) {
                float best = 3.4e38f; int bi = 0x7FFFFFFF;
                const float4* xr = (const float4*)(x + (size_t)grow * DD);
                const float fin = runmin + MARGIN;
                for (int i = 0; i < ncnt; ++i) {
                    if (cd[i] <= fin) {
                        const int code = cc[i];
                        const float4* cr = (const float4*)(cbk + code * DD);
                        float dot = 0.0f;
                        #pragma unroll
                        for (int k4 = 0; k4 < 16; ++k4) {
                            float4 a = __ldg(xr + k4);
                            float4 b = __ldg(cr + k4);
                            dot = __fmaf_rn(a.x, b.x, dot);
                            dot = __fmaf_rn(a.y, b.y, dot);
                            dot = __fmaf_rn(a.z, b.z, dot);
                            dot = __fmaf_rn(a.w, b.w, dot);
                        }
                        float t = __fadd_rn(xs, Cs[code]);
                        float d = __fmaf_rn(-2.0f, dot, t);
                        if (d < best || (d == best && code < bi)) { best = d; bi = code; }
                    }
                }
                out[2 * nD + grow] = (float)bi;
                const float4* cr = (const float4*)(cbk + bi * DD);
                float4* o0 = (float4*)(out + (size_t)grow * DD);
                float4* o1 = (float4*)(out + nD + (size_t)grow * DD);
                #pragma unroll
                for (int k4 = 0; k4 < 16; ++k4) {
                    float4 v = __ldg(cr + k4);
                    o0[k4] = v; o1[k4] = v;
                }
            }
            mbar_arrive(sb + MB_AFREE(buf));
        }
    } else if (wid < 8) {
        // ================= L: x loader + h-split, thread = row =================
        const int row = tid - 128;
        for (int it = 0; it < nt; ++it) {
            const int tile = bid + it * NCTA;
            const int grow = tile * ROWSB + row;
            const int buf = it & 1;
            if (it >= 2) mbar_wait(sb + MB_AFREE(buf), (uint32_t)(((it >> 1) + 1) & 1));

            float4 f[16];
            if (grow < n) {
                const float4* xr = (const float4*)(x + (size_t)grow * DD);
                #pragma unroll
                for (int k4 = 0; k4 < 16; ++k4) f[k4] = __ldg(xr + k4);
            } else {
                #pragma unroll
                for (int k4 = 0; k4 < 16; ++k4) f[k4] = make_float4(0.f, 0.f, 0.f, 0.f);
            }
            // exact xsq, reference order
            float s = 0.0f;
            #pragma unroll
            for (int k4 = 0; k4 < 16; ++k4) {
                s = __fadd_rn(s, __fmul_rn(f[k4].x, f[k4].x));
                s = __fadd_rn(s, __fmul_rn(f[k4].y, f[k4].y));
                s = __fadd_rn(s, __fmul_rn(f[k4].z, f[k4].z));
                s = __fadd_rn(s, __fmul_rn(f[k4].w, f[k4].w));
            }
            XsS[buf * 128 + row] = s;
            // h-limb to A[buf], SW128 (16B chunks)
            #pragma unroll
            for (int c8 = 0; c8 < 8; ++c8) {
                float4 a = f[c8 * 2], b = f[c8 * 2 + 1];
                uint4 u;
                u.x = packbf(a.x, a.y); u.y = packbf(a.z, a.w);
                u.z = packbf(b.x, b.y); u.w = packbf(b.z, b.w);
                *(uint4*)(smem + A_OFF(buf) + sw128(row * 128 + c8 * 16)) = u;
            }
            fence_async();
            mbar_arrive(sb + MB_ARDY(buf));
        }
    } else {
        // ================= MMA issuer (warp 8) =================
        if (elect1()) {
            const uint64_t bdesc = mk_desc(sb + B_OFF);
            for (int it = 0; it < nt; ++it) {
                const int buf = it & 1;
                mbar_wait(sb + MB_ARDY(buf), (uint32_t)((it >> 1) & 1));
                const uint64_t adesc = mk_desc(sb + A_OFF(buf));
                for (int q = 0; q < 4; ++q) {
                    if (it > 0) mbar_wait(sb + MB_DFREE(q), (uint32_t)((it + 1) & 1));
                    const uint64_t bq = bdesc + (uint32_t)(q * 128 * 128 / 16);
                    const uint32_t dcol = tmem + q * 128;
                    #pragma unroll
                    for (int k = 0; k < 4; ++k)
                        mma_f16_ss(dcol, adesc + k * 2, bq + k * 2, IDESC, k != 0);
                    mma_commit(sb + MB_DFULL(q));
                }
            }
        }
    }

    __syncthreads();
    if (wid == 8) tmem_dealloc(tmem, 512);

#else
    // ============ generic-arch fallback (compile-only on GB300) ============
    for (int c = tid; c < KC; c += NTHR) {
        float s = 0.0f;
        const float* cr = cbk + c * DD;
        for (int k = 0; k < DD; ++k) {
            float v = cr[k];
            s = __fadd_rn(s, __fmul_rn(v, v));
        }
        Cs[c] = s;
    }
    __syncthreads();
    for (long long row = (long long)bid * NTHR + tid; row < n; row += (long long)gridDim.x * NTHR) {
        const float* xr = x + row * DD;
        float xv[DD];
        for (int k = 0; k < DD; ++k) xv[k] = xr[k];
        float xs = 0.0f;
        for (int k = 0; k < DD; ++k) xs = __fadd_rn(xs, __fmul_rn(xv[k], xv[k]));
        float best = 3.4e38f; int bi = 0;
        for (int c = 0; c < KC; ++c) {
            const float* cr = cbk + c * DD;
            float dot = 0.0f;
            for (int k = 0; k < DD; ++k) dot = __fmaf_rn(xv[k], cr[k], dot);
            float d = __fmaf_rn(-2.0f, dot, __fadd_rn(xs, Cs[c]));
            if (d < best) { best = d; bi = c; }
        }
        out[2 * nD + row] = (float)bi;
        const float* cr = cbk + bi * DD;
        for (int k = 0; k < DD; ++k) {
            out[(size_t)row * DD + k] = cr[k];
            out[nD + (size_t)row * DD + k] = cr[k];
        }
    }
#endif
}

extern "C" void kernel_launch(void* const* d_in, const int* in_sizes, int n_in,
                              void* d_out, int out_size) {
    const float* x = (const float*)d_in[0];
    const float* cbk = (const float*)d_in[1];
    float* out = (float*)d_out;
    const int n = in_sizes[0] / DD;

    cudaFuncSetAttribute(vq_persist, cudaFuncAttributeMaxDynamicSharedMemorySize, SMEM_TOTAL);
    vq_persist<<<NCTA, NTHR, SMEM_TOTAL>>>(x, cbk, out, n);
}

// round 7
// speedup vs baseline: 2.8217x; 2.8217x over previous
#include <cuda_runtime.h>
#include <cuda_bf16.h>
#include <cstdint>

#define DD 64
#define KC 512
#define ROWSB 128
#define NTHR 256
#define NCTA 148
#define CAP 16
#define MARGIN 5e-3f

#if defined(__CUDA_ARCH__) && (defined(__CUDA_ARCH_FEAT_SM103_ALL) || defined(__CUDA_ARCH_FEAT_SM100_ALL) || defined(__CUDA_ARCH_FEAT_SM101_ALL))
#define HAS_TCGEN05 1
#else
#define HAS_TCGEN05 0
#endif

// ---- smem byte offsets ----
#define MB_MDONE   0          // count 1, flips once per tile
#define TMEM_SLOT  16
#define CS_OFF     128        // 512 f32
#define XS_OFF     2176       // 2 x 128 f32
#define BD_OFF     3200       // 2 x 128 f32 (per-half best exact dist)
#define BI_OFF     4224       // 2 x 128 int
#define SIDX_OFF   5248       // 128 int
#define B_OFF      8192       // 64KB bf16 h-limb, SW128 (1024-aligned)
#define A_OFF(b)   (73728 + (b) * 16384)
#define SMEM_TOTAL 106496

__device__ __forceinline__ uint32_t smem_u32(const void* p) {
    uint32_t a;
    asm("{ .reg .u64 t; cvta.to.shared.u64 t, %1; cvt.u32.u64 %0, t; }" : "=r"(a) : "l"(p));
    return a;
}
__device__ __forceinline__ uint32_t sw128(uint32_t off) { return off ^ ((off >> 3) & 0x70); }

#if HAS_TCGEN05
__device__ __forceinline__ uint32_t elect1() {
    uint32_t p;
    asm volatile("{ .reg .pred p; elect.sync _|p, 0xFFFFFFFF; selp.b32 %0, 1, 0, p; }" : "=r"(p));
    return p;
}
__device__ __forceinline__ void mbar_init(uint32_t a, uint32_t cnt) {
    asm volatile("mbarrier.init.shared.b64 [%0], %1;" :: "r"(a), "r"(cnt) : "memory");
}
__device__ __forceinline__ void mbar_wait(uint32_t a, uint32_t parity) {
    asm volatile(
        "{\n\t.reg .pred P;\n"
        "WL_%=:\n\t"
        "mbarrier.try_wait.parity.acquire.cta.shared::cta.b64 P, [%0], %1, 0x989680;\n\t"
        "@!P bra WL_%=;\n\t}"
        :: "r"(a), "r"(parity) : "memory");
}
__device__ __forceinline__ void fence_async() {
    asm volatile("fence.proxy.async.shared::cta;" ::: "memory");
}
__device__ __forceinline__ void tmem_alloc(uint32_t slot, uint32_t ncols) {
    asm volatile("tcgen05.alloc.cta_group::1.sync.aligned.shared::cta.b32 [%0], %1;"
                 :: "r"(slot), "r"(ncols) : "memory");
}
__device__ __forceinline__ void tmem_dealloc(uint32_t base, uint32_t ncols) {
    asm volatile("tcgen05.dealloc.cta_group::1.sync.aligned.b32 %0, %1;" :: "r"(base), "r"(ncols));
}
__device__ __forceinline__ void mma_f16_ss(uint32_t d, uint64_t ad, uint64_t bd,
                                           uint32_t idesc, uint32_t en) {
    asm volatile(
        "{\n\t.reg .pred p;\n\t"
        "setp.ne.u32 p, %5, 0;\n\t"
        "tcgen05.mma.cta_group::1.kind::f16 [%0], %1, %2, %3, {%4, %4, %4, %4}, p;\n\t}"
        :: "r"(d), "l"(ad), "l"(bd), "r"(idesc), "r"(0u), "r"(en) : "memory");
}
__device__ __forceinline__ void mma_commit(uint32_t mbar) {
    asm volatile("tcgen05.commit.cta_group::1.mbarrier::arrive::one.shared::cluster.b64 [%0];"
                 :: "r"(mbar) : "memory");
}
__device__ __forceinline__ void fence_tc_after() {
    asm volatile("tcgen05.fence::after_thread_sync;" ::: "memory");
}
__device__ __forceinline__ void fence_tc_before() {
    asm volatile("tcgen05.fence::before_thread_sync;" ::: "memory");
}
#define LDTM_X32(r, a) \
    asm volatile("tcgen05.ld.sync.aligned.32x32b.x32.b32 " \
        "{%0,%1,%2,%3,%4,%5,%6,%7,%8,%9,%10,%11,%12,%13,%14,%15," \
        "%16,%17,%18,%19,%20,%21,%22,%23,%24,%25,%26,%27,%28,%29,%30,%31}, [%32];" \
        : "=r"((r)[0]),"=r"((r)[1]),"=r"((r)[2]),"=r"((r)[3]),"=r"((r)[4]),"=r"((r)[5]), \
          "=r"((r)[6]),"=r"((r)[7]),"=r"((r)[8]),"=r"((r)[9]),"=r"((r)[10]),"=r"((r)[11]), \
          "=r"((r)[12]),"=r"((r)[13]),"=r"((r)[14]),"=r"((r)[15]),"=r"((r)[16]),"=r"((r)[17]), \
          "=r"((r)[18]),"=r"((r)[19]),"=r"((r)[20]),"=r"((r)[21]),"=r"((r)[22]),"=r"((r)[23]), \
          "=r"((r)[24]),"=r"((r)[25]),"=r"((r)[26]),"=r"((r)[27]),"=r"((r)[28]),"=r"((r)[29]), \
          "=r"((r)[30]),"=r"((r)[31]) : "r"(a))
__device__ __forceinline__ void tmem_wait_ld() {
    asm volatile("tcgen05.wait::ld.sync.aligned;" ::: "memory");
}
#endif

#define DESC_BASE 0x4000404000010000ULL
__device__ __forceinline__ uint64_t mk_desc(uint32_t addr) {
    return DESC_BASE | ((uint64_t)(addr >> 4) & 0x3FFF);
}
#define IDESC 0x8200490u   // f32 acc, bf16 a/b, M=128, N=128 (proven R3-R6)

__device__ __forceinline__ uint32_t packbf(float a, float b) {
    return (uint32_t)__bfloat16_as_ushort(__float2bfloat16(a)) |
           ((uint32_t)__bfloat16_as_ushort(__float2bfloat16(b)) << 16);
}

__global__ void __launch_bounds__(NTHR, 1)
vq_persist(const float* __restrict__ x, const float* __restrict__ cbk,
           float* __restrict__ out, int n) {
    extern __shared__ char smem[];
    const int tid = threadIdx.x;
    const int bid = blockIdx.x;
    const size_t nD = (size_t)n * DD;
    float* Cs = (float*)(smem + CS_OFF);

#if HAS_TCGEN05
    const uint32_t sb = smem_u32(smem);
    const int wid = tid >> 5;
    const int lane = tid & 31;
    float* XsS = (float*)(smem + XS_OFF);
    float* BD = (float*)(smem + BD_OFF);
    int* BI = (int*)(smem + BI_OFF);
    int* sidx = (int*)(smem + SIDX_OFF);

    const int ntiles = (n + ROWSB - 1) / ROWSB;
    const int nt = (ntiles > bid) ? (ntiles - bid + NCTA - 1) / NCTA : 0;

    // ---------- startup ----------
    if (tid == 0) mbar_init(sb + MB_MDONE, 1);
    if (wid == 0) tmem_alloc(sb + TMEM_SLOT, 512);

    // B h-limb: 512x64 -> bf16 SW128 (128B per code row)
    for (int i = tid; i < KC * DD / 4; i += NTHR) {
        int code = i >> 4, kq = i & 15;
        float4 v = __ldg(((const float4*)cbk) + i);
        uint64_t u = (uint64_t)packbf(v.x, v.y) | ((uint64_t)packbf(v.z, v.w) << 32);
        *(uint64_t*)(smem + B_OFF + sw128(code * 128 + kq * 8)) = u;
    }
    // exact csq (reference rounding order)
    for (int c = tid; c < KC; c += NTHR) {
        float s = 0.0f;
        const float* cr = cbk + c * DD;
        for (int k = 0; k < DD; ++k) {
            float v = __ldg(cr + k);
            s = __fadd_rn(s, __fmul_rn(v, v));
        }
        Cs[c] = s;
    }
    // build A[0] for tile 0
    if (tid < 128 && nt > 0) {
        const int grow = bid * ROWSB + tid;
        float4 f[16];
        if (grow < n) {
            const float4* xr = (const float4*)(x + (size_t)grow * DD);
            #pragma unroll
            for (int k4 = 0; k4 < 16; ++k4) f[k4] = __ldg(xr + k4);
        } else {
            #pragma unroll
            for (int k4 = 0; k4 < 16; ++k4) f[k4] = make_float4(0.f, 0.f, 0.f, 0.f);
        }
        float s = 0.0f;
        #pragma unroll
        for (int k4 = 0; k4 < 16; ++k4) {
            s = __fadd_rn(s, __fmul_rn(f[k4].x, f[k4].x));
            s = __fadd_rn(s, __fmul_rn(f[k4].y, f[k4].y));
            s = __fadd_rn(s, __fmul_rn(f[k4].z, f[k4].z));
            s = __fadd_rn(s, __fmul_rn(f[k4].w, f[k4].w));
        }
        XsS[tid] = s;
        #pragma unroll
        for (int c8 = 0; c8 < 8; ++c8) {
            float4 a = f[c8 * 2], b = f[c8 * 2 + 1];
            uint4 u;
            u.x = packbf(a.x, a.y); u.y = packbf(a.z, a.w);
            u.z = packbf(b.x, b.y); u.w = packbf(b.z, b.w);
            *(uint4*)(smem + A_OFF(0) + sw128(tid * 128 + c8 * 16)) = u;
        }
    }
    fence_async();
    __syncthreads();
    const uint32_t tmem = *(volatile uint32_t*)(smem + TMEM_SLOT);

    const int sub = wid & 3;
    const int wg = wid >> 2;              // code half: 0 -> [0,256), 1 -> [256,512)
    const int srow = sub * 32 + lane;     // scan row
    const int cbase = wg * 256;
    const uint64_t bdesc = mk_desc(sb + B_OFF);

    // ---------- main loop ----------
    for (int it = 0; it < nt; ++it) {
        const int buf = it & 1;
        const int tile = bid + it * NCTA;

        // 1) issue MMAs for this tile (TMEM free: previous iter's reads done pre-sync)
        if (wid == 0) {
            if (elect1()) {
                const uint64_t adesc = mk_desc(sb + A_OFF(buf));
                for (int q = 0; q < 4; ++q) {
                    const uint64_t bq = bdesc + (uint32_t)(q * 1024);
                    const uint32_t dcol = tmem + q * 128;
                    #pragma unroll
                    for (int k = 0; k < 4; ++k)
                        mma_f16_ss(dcol, adesc + k * 2, bq + k * 2, IDESC, k != 0);
                }
                mma_commit(sb + MB_MDONE);
            }
        }

        // 2) build A[buf^1] for tile it+1 (overlaps the MMA)
        if (tid < 128 && it + 1 < nt) {
            const int grow2 = (bid + (it + 1) * NCTA) * ROWSB + tid;
            float4 f[16];
            if (grow2 < n) {
                const float4* xr = (const float4*)(x + (size_t)grow2 * DD);
                #pragma unroll
                for (int k4 = 0; k4 < 16; ++k4) f[k4] = __ldg(xr + k4);
            } else {
                #pragma unroll
                for (int k4 = 0; k4 < 16; ++k4) f[k4] = make_float4(0.f, 0.f, 0.f, 0.f);
            }
            float s = 0.0f;
            #pragma unroll
            for (int k4 = 0; k4 < 16; ++k4) {
                s = __fadd_rn(s, __fmul_rn(f[k4].x, f[k4].x));
                s = __fadd_rn(s, __fmul_rn(f[k4].y, f[k4].y));
                s = __fadd_rn(s, __fmul_rn(f[k4].z, f[k4].z));
                s = __fadd_rn(s, __fmul_rn(f[k4].w, f[k4].w));
            }
            XsS[(buf ^ 1) * 128 + tid] = s;
            #pragma unroll
            for (int c8 = 0; c8 < 8; ++c8) {
                float4 a = f[c8 * 2], b = f[c8 * 2 + 1];
                uint4 u;
                u.x = packbf(a.x, a.y); u.y = packbf(a.z, a.w);
                u.z = packbf(b.x, b.y); u.w = packbf(b.z, b.w);
                *(uint4*)(smem + A_OFF(buf ^ 1) + sw128(tid * 128 + c8 * 16)) = u;
            }
            fence_async();
        }

        // 3) wait MMA (normally already complete -> try_wait fast path)
        mbar_wait(sb + MB_MDONE, (uint32_t)(it & 1));
        fence_tc_after();

        // 4) scan this thread's (row, code-half): filter + exact refine
        const int grow = tile * ROWSB + srow;
        const float xs = XsS[buf * 128 + srow];
        float runmin = 3.4e38f, thrv = 3.4e38f;
        float cd[CAP]; int cc[CAP]; int ncnt = 0;

        for (int b = 0; b < 8; ++b) {
            uint32_t rg[32];
            LDTM_X32(rg, tmem + cbase + b * 32);
            tmem_wait_ld();
            const int base = cbase + b * 32;
            #pragma unroll
            for (int j4 = 0; j4 < 8; ++j4) {
                float4 cs4 = *(const float4*)(Cs + base + j4 * 4);
                #pragma unroll
                for (int jj = 0; jj < 4; ++jj) {
                    const int j = j4 * 4 + jj;
                    float csv = (jj == 0) ? cs4.x : (jj == 1) ? cs4.y : (jj == 2) ? cs4.z : cs4.w;
                    float dot = __uint_as_float(rg[j]);
                    float dist = __fmaf_rn(-2.0f, dot, xs + csv);
                    if (dist <= thrv) {   // rare
                        if (ncnt < CAP) {
                            cd[ncnt] = dist; cc[ncnt] = base + j; ++ncnt;
                        } else {
                            int mi = 0; float mv = cd[0];
                            #pragma unroll
                            for (int i2 = 1; i2 < CAP; ++i2)
                                if (cd[i2] > mv) { mv = cd[i2]; mi = i2; }
                            if (dist < mv) { cd[mi] = dist; cc[mi] = base + j; }
                        }
                        if (dist < runmin) { runmin = dist; thrv = runmin + MARGIN; }
                    }
                }
            }
        }

        float best = 3.4e38f; int bi = 0x7FFFFFFF;
        if (grow < n) {
            const float4* xr = (const float4*)(x + (size_t)grow * DD);
            const float fin = runmin + MARGIN;
            for (int i = 0; i < ncnt; ++i) {
                if (cd[i] <= fin) {
                    const int code = cc[i];
                    const float4* cr = (const float4*)(cbk + code * DD);
                    float dot = 0.0f;
                    #pragma unroll
                    for (int k4 = 0; k4 < 16; ++k4) {
                        float4 a = __ldg(xr + k4);
                        float4 b = __ldg(cr + k4);
                        dot = __fmaf_rn(a.x, b.x, dot);
                        dot = __fmaf_rn(a.y, b.y, dot);
                        dot = __fmaf_rn(a.z, b.z, dot);
                        dot = __fmaf_rn(a.w, b.w, dot);
                    }
                    float t = __fadd_rn(xs, Cs[code]);
                    float d = __fmaf_rn(-2.0f, dot, t);
                    if (d < best || (d == best && code < bi)) { best = d; bi = code; }
                }
            }
        }
        BD[wg * 128 + srow] = best;
        BI[wg * 128 + srow] = bi;

        fence_tc_before();      // TMEM reads done before next tile's MMA (WAR)
        __syncthreads();

        // 5) merge halves (exact dists; equal -> lower code = half 0)
        if (tid < 128) {
            float d0 = BD[tid], d1 = BD[128 + tid];
            int i0 = BI[tid], i1 = BI[128 + tid];
            int w = (d1 < d0) ? i1 : i0;
            sidx[tid] = w;
            const int g = tile * ROWSB + tid;
            if (g < n) out[2 * nD + g] = (float)w;
        }
        __syncthreads();

        // 6) gather z_q_x / z_q_x_bar (coalesced-ish, all 256 threads)
        for (int i = tid; i < ROWSB * 32; i += NTHR) {
            const int row = i >> 5;
            const int d = (i >> 4) & 1;
            const int q = i & 15;
            const int g = tile * ROWSB + row;
            if (g < n) {
                float4 v = __ldg(((const float4*)cbk) + sidx[row] * 16 + q);
                ((float4*)(out + (size_t)d * nD + (size_t)g * DD))[q] = v;
            }
        }
        // no extra sync: next iter's sidx/BD/BI writes happen after its own __syncthreads()
    }

    __syncthreads();
    if (wid == 0) tmem_dealloc(tmem, 512);

#else
    // ============ generic-arch fallback (compile-only on GB300) ============
    for (int c = tid; c < KC; c += NTHR) {
        float s = 0.0f;
        const float* cr = cbk + c * DD;
        for (int k = 0; k < DD; ++k) {
            float v = cr[k];
            s = __fadd_rn(s, __fmul_rn(v, v));
        }
        Cs[c] = s;
    }
    __syncthreads();
    for (long long row = (long long)bid * NTHR + tid; row < n; row += (long long)gridDim.x * NTHR) {
        const float* xr = x + row * DD;
        float xv[DD];
        for (int k = 0; k < DD; ++k) xv[k] = xr[k];
        float xs = 0.0f;
        for (int k = 0; k < DD; ++k) xs = __fadd_rn(xs, __fmul_rn(xv[k], xv[k]));
        float best = 3.4e38f; int bi = 0;
        for (int c = 0; c < KC; ++c) {
            const float* cr = cbk + c * DD;
            float dot = 0.0f;
            for (int k = 0; k < DD; ++k) dot = __fmaf_rn(xv[k], cr[k], dot);
            float d = __fmaf_rn(-2.0f, dot, __fadd_rn(xs, Cs[c]));
            if (d < best) { best = d; bi = c; }
        }
        out[2 * nD + row] = (float)bi;
        const float* cr = cbk + bi * DD;
        for (int k = 0; k < DD; ++k) {
            out[(size_t)row * DD + k] = cr[k];
            out[nD + (size_t)row * DD + k] = cr[k];
        }
    }
#endif
}

extern "C" void kernel_launch(void* const* d_in, const int* in_sizes, int n_in,
                              void* d_out, int out_size) {
    const float* x = (const float*)d_in[0];
    const float* cbk = (const float*)d_in[1];
    float* out = (float*)d_out;
    const int n = in_sizes[0] / DD;

    cudaFuncSetAttribute(vq_persist, cudaFuncAttributeMaxDynamicSharedMemorySize, SMEM_TOTAL);
    vq_persist<<<NCTA, NTHR, SMEM_TOTAL>>>(x, cbk, out, n);
}